// round 13
// baseline (speedup 1.0000x reference)
#include <cuda_runtime.h>
#include <cuda.h>
#include <cstdint>

#define MROWS 128
#define KDIM  4096
#define NDIM  16384
#define NTILE 128
#define KC    128
#define NKC   (KDIM / KC)
#define NSTAGES 3

#define SM_FULL(s)  (16 + (s) * 8)
#define SM_EMPTY(s) (80 + (s) * 8)
#define STAGE_BYTES (3 * 128 * KC)              // 48KB
#define SM_STAGE0   1024
#define OFF_Q1 0
#define OFF_Q2 (128 * KC)
#define OFF_W  (2 * 128 * KC)
#define WSTG0       (SM_STAGE0 + NSTAGES * STAGE_BYTES)   // 148480
#define WSTG_BYTES  65536
#define SMEM_TOTAL  (WSTG0 + WSTG_BYTES)        // 214016 <= 232448

#define SWZ(o) ((uint32_t)(o) ^ ((((uint32_t)(o)) >> 3) & 0x70u))

__device__ __align__(128) int8_t g_q1[MROWS * KDIM];
__device__ __align__(128) int8_t g_q2[MROWS * KDIM];
__device__ float g_s1[MROWS];
__device__ float g_s2[MROWS];
__device__ int   g_swap;
__device__ int   g_wfmt;   // 0=int8 packed, 1=int32, 2=float32, 3=bf16

__device__ __forceinline__ uint32_t smem_u32(const void* p) {
    uint32_t a;
    asm("{ .reg .u64 t; cvta.to.shared.u64 t, %1; cvt.u32.u64 %0, t; }" : "=r"(a) : "l"(p));
    return a;
}
__device__ __forceinline__ void mbar_init(uint32_t m, uint32_t c) {
    asm volatile("mbarrier.init.shared.b64 [%0], %1;" :: "r"(m), "r"(c) : "memory");
}
__device__ __forceinline__ void mbar_expect_tx(uint32_t m, uint32_t b) {
    asm volatile("mbarrier.arrive.expect_tx.shared.b64 _, [%0], %1;" :: "r"(m), "r"(b) : "memory");
}
__device__ __forceinline__ void mbar_arrive(uint32_t m) {
    asm volatile("mbarrier.arrive.shared.b64 _, [%0];" :: "r"(m) : "memory");
}
// acquire wait: REQUIRED before any generic ld/st.shared that follows
__device__ __forceinline__ void mbar_wait(uint32_t m, uint32_t p) {
    asm volatile(
        "{\n\t.reg .pred P1;\n\tW_%=:\n\t"
        "mbarrier.try_wait.parity.acquire.cta.shared::cta.b64 P1, [%0], %1, 0x989680;\n\t"
        "@P1 bra.uni D_%=;\n\tbra.uni W_%=;\n\tD_%=:\n\t}"
        :: "r"(m), "r"(p) : "memory");
}
__device__ __forceinline__ void tma2d(uint32_t d, const CUtensorMap* t,
                                      int32_t cx, int32_t cy, uint32_t m) {
    asm volatile(
        "cp.async.bulk.tensor.2d.shared::cta.global.tile.mbarrier::complete_tx::bytes "
        "[%0], [%1, {%2, %3}], [%4];"
        :: "r"(d), "l"(t), "r"(cx), "r"(cy), "r"(m) : "memory");
}
__device__ __forceinline__ void cpasync16(uint32_t dst, const void* src) {
    asm volatile("cp.async.cg.shared.global [%0], [%1], 16;" :: "r"(dst), "l"(src) : "memory");
}
#define CP_COMMIT() asm volatile("cp.async.commit_group;" ::: "memory")
#define CP_WAIT0()  asm volatile("cp.async.wait_group 0;" ::: "memory")

__device__ __forceinline__ void sts128(uint32_t addr, int4 v) {
    asm volatile("st.shared.v4.b32 [%0], {%1,%2,%3,%4};"
                 :: "r"(addr), "r"(v.x), "r"(v.y), "r"(v.z), "r"(v.w) : "memory");
}
#define LDS128(v, a)                                                          \
    asm volatile("ld.shared.v4.b32 {%0,%1,%2,%3}, [%4];"                      \
                 : "=r"((v).x), "=r"((v).y), "=r"((v).z), "=r"((v).w) : "r"(a))

#define LDMX4(r, addr)                                                           \
    asm volatile("ldmatrix.sync.aligned.m8n8.x4.shared.b16 {%0,%1,%2,%3}, [%4];" \
                 : "=r"((r)[0]), "=r"((r)[1]), "=r"((r)[2]), "=r"((r)[3])        \
                 : "r"(addr))

#define MMA_S8(c, a, b0, b1)                                                  \
    asm volatile("mma.sync.aligned.m16n8k32.row.col.s32.s8.s8.s32 "           \
                 "{%0,%1,%2,%3}, {%4,%5,%6,%7}, {%8,%9}, {%0,%1,%2,%3};"      \
                 : "+r"((c)[0]), "+r"((c)[1]), "+r"((c)[2]), "+r"((c)[3])     \
                 : "r"((a)[0]), "r"((a)[1]), "r"((a)[2]), "r"((a)[3]),        \
                   "r"(b0), "r"(b1))

__device__ __forceinline__ int pack4i(int x0, int x1, int x2, int x3) {
    return (x0 & 0xFF) | ((x1 & 0xFF) << 8) | ((x2 & 0xFF) << 16) | ((x3 & 0xFF) << 24);
}
__device__ __forceinline__ int bf2i(uint32_t h) {
    return __float2int_rn(__uint_as_float(h << 16));
}

// ============================================================
// quantize + detect fused (blocks 0-127 quantize, 128/129 detect)
// ============================================================
__global__ void __launch_bounds__(256) quantize_x_kernel(const float* __restrict__ x,
                                                         const int* __restrict__ wsrc,
                                                         const float* __restrict__ f0) {
    int tid = threadIdx.x;
    if (blockIdx.x == 128) {
        int ok_i32 = 1, ok_f32 = 1, ok_bf16 = 1;
#pragma unroll
        for (int t = 0; t < 4; t++) {
            int w = wsrc[tid + t * 256];
            if (w < -128 || w > 127) ok_i32 = 0;
            float f = __int_as_float(w);
            if (!(f == rintf(f) && fabsf(f) <= 127.0f)) ok_f32 = 0;
            float h0 = __uint_as_float(((uint32_t)w & 0xFFFFu) << 16);
            float h1 = __uint_as_float(((uint32_t)w >> 16) << 16);
            if (!(h0 == rintf(h0) && fabsf(h0) <= 127.0f)) ok_bf16 = 0;
            if (!(h1 == rintf(h1) && fabsf(h1) <= 127.0f)) ok_bf16 = 0;
        }
        ok_i32  = __syncthreads_and(ok_i32);
        ok_f32  = __syncthreads_and(ok_f32);
        ok_bf16 = __syncthreads_and(ok_bf16);
        if (tid == 0) g_wfmt = ok_i32 ? 1 : (ok_f32 ? 2 : (ok_bf16 ? 3 : 0));
        return;
    }
    if (blockIdx.x == 129) {
        __shared__ int neg;
        if (tid == 0) neg = 0;
        __syncthreads();
        int found = 0;
        for (int i = tid; i < NDIM; i += 256) found |= (f0[i] < 0.0f);
        if (__any_sync(0xFFFFFFFFu, found) && (tid & 31) == 0) atomicOr(&neg, 1);
        __syncthreads();
        if (tid == 0) g_swap = neg;
        return;
    }

    int row = blockIdx.x;
    const float4* xr = reinterpret_cast<const float4*>(x + (size_t)row * KDIM);
    float4 v[4];
    float amax = 0.f;
#pragma unroll
    for (int i = 0; i < 4; i++) {
        v[i] = xr[tid + i * 256];
        amax = fmaxf(amax, fmaxf(fmaxf(fabsf(v[i].x), fabsf(v[i].y)),
                                 fmaxf(fabsf(v[i].z), fabsf(v[i].w))));
    }
#pragma unroll
    for (int o = 16; o > 0; o >>= 1) amax = fmaxf(amax, __shfl_xor_sync(0xFFFFFFFFu, amax, o));
    __shared__ float wmax[8];
    if ((tid & 31) == 0) wmax[tid >> 5] = amax;
    __syncthreads();
    float am = wmax[0];
#pragma unroll
    for (int w = 1; w < 8; w++) am = fmaxf(am, wmax[w]);
    am = fmaxf(am, 1e-20f);

    float s1 = am * (1.0f / 127.0f), inv1 = 127.0f / am;
    float s2 = s1 * (1.0f / 254.0f), inv2 = 254.0f / s1;
    if (tid == 0) { g_s1[row] = s1; g_s2[row] = s2; }

    char4* q1o = reinterpret_cast<char4*>(g_q1 + (size_t)row * KDIM);
    char4* q2o = reinterpret_cast<char4*>(g_q2 + (size_t)row * KDIM);
#pragma unroll
    for (int i = 0; i < 4; i++) {
        float f[4] = {v[i].x, v[i].y, v[i].z, v[i].w};
        signed char c1[4], c2[4];
#pragma unroll
        for (int j = 0; j < 4; j++) {
            int q1 = __float2int_rn(f[j] * inv1);
            q1 = max(-127, min(127, q1));
            float r = f[j] - s1 * (float)q1;
            int q2 = __float2int_rn(r * inv2);
            q2 = max(-127, min(127, q2));
            c1[j] = (signed char)q1;
            c2[j] = (signed char)q2;
        }
        q1o[tid + i * 256] = make_char4(c1[0], c1[1], c1[2], c1[3]);
        q2o[tid + i * 256] = make_char4(c2[0], c2[1], c2[2], c2[3]);
    }
}

// ============================================================
// Fused GEMM, 3-stage pipeline. 384 threads: wid 0-7 consumers,
// wid 8-11 W producers (coalesced cp.async into single 64KB staging,
// pack -> swizzled STS). Producers run up to 3 stages ahead, hiding
// q-TMA flight and pack latency that bubbled the 2-stage pipeline.
// ============================================================
__global__ void __launch_bounds__(384, 1) Linear8bit_gemm(
    const __grid_constant__ CUtensorMap tm_q1,
    const __grid_constant__ CUtensorMap tm_q2,
    const void* __restrict__ wsrc,
    const float* __restrict__ f0,
    const float* __restrict__ f1,
    float* __restrict__ out)
{
    extern __shared__ __align__(1024) uint8_t smem_buf[];
    uint32_t sb = smem_u32(smem_buf);
    int tid = threadIdx.x, wid = tid >> 5, lane = tid & 31;
    int n0 = blockIdx.x * NTILE;
    int fmt = g_wfmt;

    if (tid == 0) {
        for (int s = 0; s < NSTAGES; s++) {
            mbar_init(sb + SM_FULL(s), 129);  // 1 expect_tx + 128 producer arrivals
            mbar_init(sb + SM_EMPTY(s), 8);   // 8 consumer warps
        }
    }
    asm volatile("fence.proxy.async.shared::cta;" ::: "memory");
    __syncthreads();

    int c[4][8][4];
#pragma unroll
    for (int i = 0; i < 4; i++)
#pragma unroll
        for (int j = 0; j < 8; j++)
#pragma unroll
            for (int q = 0; q < 4; q++) c[i][j][q] = 0;

    int ww = wid & 3;
    int wm = (ww & 1) * 64;
    int wn = (ww >> 1) * 64;

    if (wid >= 8) {
        int ptid = tid - 256;              // 0..127, owns W row ptid
        int pwarp = ptid >> 5;             // producer warp 0..3
        if (fmt == 1 || fmt == 2) {
            // ---- coalesced cp.async staged producer, single 64KB buffer ----
            const char* base = (const char*)wsrc;
            uint32_t stg = sb + WSTG0;
            // prefetch stage 0 (warp loads its 32 rows; lane l -> bytes l*16)
            {
                for (int r = 0; r < 32; r++) {
                    int row = pwarp * 32 + r;
                    cpasync16(stg + (uint32_t)row * 512 + lane * 16,
                              base + ((size_t)(n0 + row) * KDIM) * 4 + lane * 16);
                }
                CP_COMMIT();
            }

            int st = 0, ph = 1;
            int tx0 = ptid & 3;            // chunk-within-group permutation
            int jx0 = (ptid >> 2) & 7;     // group permutation
            uint32_t srow = stg + (uint32_t)ptid * 512;
            uint32_t dbase = (uint32_t)ptid * 128;

            for (int kc = 0; kc < NKC; kc++) {
                CP_WAIT0();
                __syncwarp();              // whole warp's slices landed
                mbar_wait(sb + SM_EMPTY(st), ph);   // ACQUIRE
                if (ptid == 0) {
                    mbar_expect_tx(sb + SM_FULL(st), 2 * 128 * KC);
                    uint32_t sbase = sb + SM_STAGE0 + st * STAGE_BYTES;
                    tma2d(sbase + OFF_Q1, &tm_q1, kc * KC, 0, sb + SM_FULL(st));
                    tma2d(sbase + OFF_Q2, &tm_q2, kc * KC, 0, sb + SM_FULL(st));
                }
                uint32_t Wb = sb + SM_STAGE0 + st * STAGE_BYTES + OFF_W;

#pragma unroll
                for (int jx = 0; jx < 8; jx++) {
                    int j = jx ^ jx0;
                    uint32_t ow[4];
#pragma unroll
                    for (int t = 0; t < 4; t++) {
                        int tc = t ^ tx0;
                        int4 v;
                        LDS128(v, srow + (uint32_t)(j * 4 + tc) * 16);
                        if (fmt == 1) {
                            ow[tc] = pack4i(v.x, v.y, v.z, v.w);
                        } else {
                            ow[tc] = pack4i(__float2int_rn(__int_as_float(v.x)),
                                            __float2int_rn(__int_as_float(v.y)),
                                            __float2int_rn(__int_as_float(v.z)),
                                            __float2int_rn(__int_as_float(v.w)));
                        }
                    }
                    int4 o = make_int4(ow[0], ow[1], ow[2], ow[3]);
                    sts128(Wb + SWZ(dbase + j * 16), o);
                }
                mbar_arrive(sb + SM_FULL(st));
                __syncwarp();              // ALL lanes done packing before refill

                int pf = kc + 1;
                if (pf < NKC) {
                    size_t go = (size_t)pf * KC * 4;
                    for (int r = 0; r < 32; r++) {
                        int row = pwarp * 32 + r;
                        cpasync16(stg + (uint32_t)row * 512 + lane * 16,
                                  base + ((size_t)(n0 + row) * KDIM) * 4 + go + lane * 16);
                    }
                    CP_COMMIT();
                }
                if (++st == NSTAGES) { st = 0; ph ^= 1; }
            }
        } else {
            // ---- LDG fallback (fmt 0 = packed int8, fmt 3 = bf16) ----
            int st = 0, ph = 1;
            for (int kc = 0; kc < NKC; kc++) {
                mbar_wait(sb + SM_EMPTY(st), ph);   // ACQUIRE
                if (ptid == 0) {
                    mbar_expect_tx(sb + SM_FULL(st), 2 * 128 * KC);
                    uint32_t sbase = sb + SM_STAGE0 + st * STAGE_BYTES;
                    tma2d(sbase + OFF_Q1, &tm_q1, kc * KC, 0, sb + SM_FULL(st));
                    tma2d(sbase + OFF_Q2, &tm_q2, kc * KC, 0, sb + SM_FULL(st));
                }
                uint32_t Wb = sb + SM_STAGE0 + st * STAGE_BYTES + OFF_W;
                uint32_t dbase = (uint32_t)ptid * 128;
                size_t e0 = (size_t)(n0 + ptid) * KDIM + (size_t)kc * KC;
                if (fmt == 3) {
                    const uint4* src = reinterpret_cast<const uint4*>(
                        (const uint16_t*)wsrc + e0);
#pragma unroll
                    for (int ch = 0; ch < 8; ch++) {
                        uint4 p0 = src[ch * 2], p1 = src[ch * 2 + 1];
                        int4 o;
                        o.x = pack4i(bf2i(p0.x & 0xFFFFu), bf2i(p0.x >> 16),
                                     bf2i(p0.y & 0xFFFFu), bf2i(p0.y >> 16));
                        o.y = pack4i(bf2i(p0.z & 0xFFFFu), bf2i(p0.z >> 16),
                                     bf2i(p0.w & 0xFFFFu), bf2i(p0.w >> 16));
                        o.z = pack4i(bf2i(p1.x & 0xFFFFu), bf2i(p1.x >> 16),
                                     bf2i(p1.y & 0xFFFFu), bf2i(p1.y >> 16));
                        o.w = pack4i(bf2i(p1.z & 0xFFFFu), bf2i(p1.z >> 16),
                                     bf2i(p1.w & 0xFFFFu), bf2i(p1.w >> 16));
                        sts128(Wb + SWZ(dbase + ch * 16), o);
                    }
                } else {
                    const int4* src = reinterpret_cast<const int4*>(
                        (const int8_t*)wsrc + e0);
#pragma unroll
                    for (int ch = 0; ch < 8; ch++) {
                        int4 o = src[ch];
                        sts128(Wb + SWZ(dbase + ch * 16), o);
                    }
                }
                mbar_arrive(sb + SM_FULL(st));
                if (++st == NSTAGES) { st = 0; ph ^= 1; }
            }
        }
    } else {
        // ---------- consumer warps (proven path, 3-stage cursor) ----------
        uint32_t offA = (wid >= 4) ? (uint32_t)OFF_Q2 : (uint32_t)OFF_Q1;
        int g = lane >> 3, idx = lane & 7;

        uint32_t aP[4], bP[4];
        {
            int rb = wm + idx + (g & 1) * 8;
            int kh = (g >> 1) * 16;
#pragma unroll
            for (int i = 0; i < 4; i++) {
                int row = rb + i * 16;
                aP[i] = sb + SM_STAGE0 + offA + row * 128 + (kh ^ ((row & 7) * 16));
            }
        }
        {
            int rb = wn + idx + (g >> 1) * 8;
            int kh = (g & 1) * 16;
#pragma unroll
            for (int j = 0; j < 4; j++) {
                int row = rb + j * 16;
                bP[j] = sb + SM_STAGE0 + OFF_W + row * 128 + (kh ^ ((row & 7) * 16));
            }
        }

        int stage = 0, ph = 0;
        for (int kc = 0; kc < NKC; kc++) {
            mbar_wait(sb + SM_FULL(stage), ph);
            uint32_t sdel = stage * STAGE_BYTES;
#pragma unroll
            for (int s = 0; s < 4; s++) {
                uint32_t a[4][4], b[4][4];
#pragma unroll
                for (int i = 0; i < 4; i++) LDMX4(a[i], (aP[i] + sdel) ^ (s * 32));
#pragma unroll
                for (int j = 0; j < 4; j++) LDMX4(b[j], (bP[j] + sdel) ^ (s * 32));
#pragma unroll
                for (int i = 0; i < 4; i++)
#pragma unroll
                    for (int jj = 0; jj < 8; jj++)
                        MMA_S8(c[i][jj], a[i], b[jj >> 1][(jj & 1) * 2],
                               b[jj >> 1][(jj & 1) * 2 + 1]);
            }
            if (lane == 0) mbar_arrive(sb + SM_EMPTY(stage));
            if (++stage == NSTAGES) { stage = 0; ph ^= 1; }
        }
    }

    // ---------- epilogue (proven path) ----------
    __syncthreads();
    int swap = g_swap;
    const float* wscale = swap ? f1 : f0;
    const float* bias   = swap ? f0 : f1;

    const int LDSF = 132;
    float* smemf = reinterpret_cast<float*>(smem_buf + SM_STAGE0);

    if (wid >= 4 && wid < 8) {
#pragma unroll
        for (int i = 0; i < 4; i++) {
#pragma unroll
            for (int j = 0; j < 8; j++) {
                int r0 = wm + i * 16 + (lane >> 2);
                int c0 = wn + j * 8 + (lane & 3) * 2;
                *reinterpret_cast<float2*>(&smemf[r0 * LDSF + c0]) =
                    make_float2((float)c[i][j][0], (float)c[i][j][1]);
                *reinterpret_cast<float2*>(&smemf[(r0 + 8) * LDSF + c0]) =
                    make_float2((float)c[i][j][2], (float)c[i][j][3]);
            }
        }
    }
    __syncthreads();

    if (wid < 4) {
#pragma unroll
        for (int i = 0; i < 4; i++) {
            int r0 = wm + i * 16 + (lane >> 2);
            float s1a = g_s1[r0],     s2a = g_s2[r0];
            float s1b = g_s1[r0 + 8], s2b = g_s2[r0 + 8];
#pragma unroll
            for (int j = 0; j < 8; j++) {
                int c0 = wn + j * 8 + (lane & 3) * 2;
                float2 wsc = *reinterpret_cast<const float2*>(wscale + n0 + c0);
                float2 bi  = *reinterpret_cast<const float2*>(bias + n0 + c0);
                wsc.x *= (1.0f / 127.0f);
                wsc.y *= (1.0f / 127.0f);
                float2 d2a = *reinterpret_cast<float2*>(&smemf[r0 * LDSF + c0]);
                float2 d2b = *reinterpret_cast<float2*>(&smemf[(r0 + 8) * LDSF + c0]);
                float2 oa, ob;
                oa.x = fmaf(fmaf(s2a, d2a.x, s1a * (float)c[i][j][0]), wsc.x, bi.x);
                oa.y = fmaf(fmaf(s2a, d2a.y, s1a * (float)c[i][j][1]), wsc.y, bi.y);
                ob.x = fmaf(fmaf(s2b, d2b.x, s1b * (float)c[i][j][2]), wsc.x, bi.x);
                ob.y = fmaf(fmaf(s2b, d2b.y, s1b * (float)c[i][j][3]), wsc.y, bi.y);
                *reinterpret_cast<float2*>(out + (size_t)r0 * NDIM + n0 + c0) = oa;
                *reinterpret_cast<float2*>(out + (size_t)(r0 + 8) * NDIM + n0 + c0) = ob;
            }
        }
    }
}

typedef CUresult (*PFN_encodeTiled)(
    CUtensorMap*, CUtensorMapDataType, cuuint32_t, void*,
    const cuuint64_t*, const cuuint64_t*, const cuuint32_t*, const cuuint32_t*,
    CUtensorMapInterleave, CUtensorMapSwizzle, CUtensorMapL2promotion,
    CUtensorMapFloatOOBfill);

static void make_map_u8(PFN_encodeTiled enc, CUtensorMap* m, void* base,
                        uint64_t d0, uint64_t d1) {
    cuuint64_t dims[2]    = {d0, d1};
    cuuint64_t strides[1] = {d0};
    cuuint32_t box[2]     = {128, 128};
    cuuint32_t es[2]      = {1, 1};
    enc(m, CU_TENSOR_MAP_DATA_TYPE_UINT8, 2, base, dims, strides, box, es,
        CU_TENSOR_MAP_INTERLEAVE_NONE, CU_TENSOR_MAP_SWIZZLE_128B,
        CU_TENSOR_MAP_L2_PROMOTION_L2_128B, CU_TENSOR_MAP_FLOAT_OOB_FILL_NONE);
}

extern "C" void kernel_launch(void* const* d_in, const int* in_sizes, int n_in,
                              void* d_out, int out_size) {
    const float* x = nullptr; const void* w = nullptr;
    const float* f0 = nullptr; const float* f1 = nullptr;
    for (int i = 0; i < n_in; i++) {
        if (in_sizes[i] == MROWS * KDIM)      x = (const float*)d_in[i];
        else if (in_sizes[i] == NDIM * KDIM)  w = d_in[i];
        else if (in_sizes[i] == NDIM) {
            if (!f0) f0 = (const float*)d_in[i];
            else     f1 = (const float*)d_in[i];
        }
    }
    float* out = (float*)d_out;

    void* pq1 = nullptr; void* pq2 = nullptr;
    cudaGetSymbolAddress(&pq1, g_q1);
    cudaGetSymbolAddress(&pq2, g_q2);

    PFN_encodeTiled enc = nullptr;
    cudaDriverEntryPointQueryResult qr;
    cudaGetDriverEntryPoint("cuTensorMapEncodeTiled", (void**)&enc,
                            cudaEnableDefault, &qr);

    CUtensorMap tq1, tq2;
    make_map_u8(enc, &tq1, pq1, KDIM, MROWS);
    make_map_u8(enc, &tq2, pq2, KDIM, MROWS);

    cudaFuncSetAttribute(Linear8bit_gemm,
                         cudaFuncAttributeMaxDynamicSharedMemorySize, SMEM_TOTAL);

    quantize_x_kernel<<<130, 256>>>(x, (const int*)w, f0);
    Linear8bit_gemm<<<NDIM / NTILE, 384, SMEM_TOTAL>>>(tq1, tq2, w, f0, f1, out);
}

// round 14
// speedup vs baseline: 3.9393x; 3.9393x over previous
#include <cuda_runtime.h>
#include <cuda.h>
#include <cstdint>

#define MROWS 128
#define KDIM  4096
#define NDIM  16384
#define NTILE 128
#define KC    128
#define NKC   (KDIM / KC)
#define NSTAGES 3

#define SM_FULL(s)  (16 + (s) * 8)
#define SM_EMPTY(s) (80 + (s) * 8)
#define STAGE_BYTES (3 * 128 * KC)              // 48KB
#define SM_STAGE0   1024
#define OFF_Q1 0
#define OFF_Q2 (128 * KC)
#define OFF_W  (2 * 128 * KC)
#define WROW        272                          // 256B + 16B pad (bank spread)
#define WSTG_HALF   (128 * WROW)                 // 34816
#define WSTG0       (SM_STAGE0 + NSTAGES * STAGE_BYTES)   // 148480
#define SMEM_TOTAL  (WSTG0 + 2 * WSTG_HALF)      // 218112 <= 232448

#define SWZ(o) ((uint32_t)(o) ^ ((((uint32_t)(o)) >> 3) & 0x70u))

__device__ __align__(128) int8_t g_q1[MROWS * KDIM];
__device__ __align__(128) int8_t g_q2[MROWS * KDIM];
__device__ float g_s1[MROWS];
__device__ float g_s2[MROWS];
__device__ int   g_swap;
__device__ int   g_wfmt;   // 0=int8 packed, 1=int32, 2=float32, 3=bf16

__device__ __forceinline__ uint32_t smem_u32(const void* p) {
    uint32_t a;
    asm("{ .reg .u64 t; cvta.to.shared.u64 t, %1; cvt.u32.u64 %0, t; }" : "=r"(a) : "l"(p));
    return a;
}
__device__ __forceinline__ void mbar_init(uint32_t m, uint32_t c) {
    asm volatile("mbarrier.init.shared.b64 [%0], %1;" :: "r"(m), "r"(c) : "memory");
}
__device__ __forceinline__ void mbar_expect_tx(uint32_t m, uint32_t b) {
    asm volatile("mbarrier.arrive.expect_tx.shared.b64 _, [%0], %1;" :: "r"(m), "r"(b) : "memory");
}
__device__ __forceinline__ void mbar_arrive(uint32_t m) {
    asm volatile("mbarrier.arrive.shared.b64 _, [%0];" :: "r"(m) : "memory");
}
// acquire wait: REQUIRED before any generic ld/st.shared that follows
__device__ __forceinline__ void mbar_wait(uint32_t m, uint32_t p) {
    asm volatile(
        "{\n\t.reg .pred P1;\n\tW_%=:\n\t"
        "mbarrier.try_wait.parity.acquire.cta.shared::cta.b64 P1, [%0], %1, 0x989680;\n\t"
        "@P1 bra.uni D_%=;\n\tbra.uni W_%=;\n\tD_%=:\n\t}"
        :: "r"(m), "r"(p) : "memory");
}
__device__ __forceinline__ void tma2d(uint32_t d, const CUtensorMap* t,
                                      int32_t cx, int32_t cy, uint32_t m) {
    asm volatile(
        "cp.async.bulk.tensor.2d.shared::cta.global.tile.mbarrier::complete_tx::bytes "
        "[%0], [%1, {%2, %3}], [%4];"
        :: "r"(d), "l"(t), "r"(cx), "r"(cy), "r"(m) : "memory");
}
__device__ __forceinline__ void cpasync16(uint32_t dst, const void* src) {
    asm volatile("cp.async.cg.shared.global [%0], [%1], 16;" :: "r"(dst), "l"(src) : "memory");
}
#define CP_COMMIT() asm volatile("cp.async.commit_group;" ::: "memory")
#define CP_WAIT1()  asm volatile("cp.async.wait_group 1;" ::: "memory")

__device__ __forceinline__ void sts128(uint32_t addr, int4 v) {
    asm volatile("st.shared.v4.b32 [%0], {%1,%2,%3,%4};"
                 :: "r"(addr), "r"(v.x), "r"(v.y), "r"(v.z), "r"(v.w) : "memory");
}
#define LDS128(v, a)                                                          \
    asm volatile("ld.shared.v4.b32 {%0,%1,%2,%3}, [%4];"                      \
                 : "=r"((v).x), "=r"((v).y), "=r"((v).z), "=r"((v).w) : "r"(a))

#define LDMX4(r, addr)                                                           \
    asm volatile("ldmatrix.sync.aligned.m8n8.x4.shared.b16 {%0,%1,%2,%3}, [%4];" \
                 : "=r"((r)[0]), "=r"((r)[1]), "=r"((r)[2]), "=r"((r)[3])        \
                 : "r"(addr))

#define MMA_S8(c, a, b0, b1)                                                  \
    asm volatile("mma.sync.aligned.m16n8k32.row.col.s32.s8.s8.s32 "           \
                 "{%0,%1,%2,%3}, {%4,%5,%6,%7}, {%8,%9}, {%0,%1,%2,%3};"      \
                 : "+r"((c)[0]), "+r"((c)[1]), "+r"((c)[2]), "+r"((c)[3])     \
                 : "r"((a)[0]), "r"((a)[1]), "r"((a)[2]), "r"((a)[3]),        \
                   "r"(b0), "r"(b1))

__device__ __forceinline__ int pack4i(int x0, int x1, int x2, int x3) {
    return (x0 & 0xFF) | ((x1 & 0xFF) << 8) | ((x2 & 0xFF) << 16) | ((x3 & 0xFF) << 24);
}
__device__ __forceinline__ int bf2i(uint32_t h) {
    return __float2int_rn(__uint_as_float(h << 16));
}

// ============================================================
// quantize + detect fused (blocks 0-127 quantize, 128/129 detect)
// ============================================================
__global__ void __launch_bounds__(256) quantize_x_kernel(const float* __restrict__ x,
                                                         const int* __restrict__ wsrc,
                                                         const float* __restrict__ f0) {
    int tid = threadIdx.x;
    if (blockIdx.x == 128) {
        int ok_i32 = 1, ok_f32 = 1, ok_bf16 = 1;
#pragma unroll
        for (int t = 0; t < 4; t++) {
            int w = wsrc[tid + t * 256];
            if (w < -128 || w > 127) ok_i32 = 0;
            float f = __int_as_float(w);
            if (!(f == rintf(f) && fabsf(f) <= 127.0f)) ok_f32 = 0;
            float h0 = __uint_as_float(((uint32_t)w & 0xFFFFu) << 16);
            float h1 = __uint_as_float(((uint32_t)w >> 16) << 16);
            if (!(h0 == rintf(h0) && fabsf(h0) <= 127.0f)) ok_bf16 = 0;
            if (!(h1 == rintf(h1) && fabsf(h1) <= 127.0f)) ok_bf16 = 0;
        }
        ok_i32  = __syncthreads_and(ok_i32);
        ok_f32  = __syncthreads_and(ok_f32);
        ok_bf16 = __syncthreads_and(ok_bf16);
        if (tid == 0) g_wfmt = ok_i32 ? 1 : (ok_f32 ? 2 : (ok_bf16 ? 3 : 0));
        return;
    }
    if (blockIdx.x == 129) {
        __shared__ int neg;
        if (tid == 0) neg = 0;
        __syncthreads();
        int found = 0;
        for (int i = tid; i < NDIM; i += 256) found |= (f0[i] < 0.0f);
        if (__any_sync(0xFFFFFFFFu, found) && (tid & 31) == 0) atomicOr(&neg, 1);
        __syncthreads();
        if (tid == 0) g_swap = neg;
        return;
    }

    int row = blockIdx.x;
    const float4* xr = reinterpret_cast<const float4*>(x + (size_t)row * KDIM);
    float4 v[4];
    float amax = 0.f;
#pragma unroll
    for (int i = 0; i < 4; i++) {
        v[i] = xr[tid + i * 256];
        amax = fmaxf(amax, fmaxf(fmaxf(fabsf(v[i].x), fabsf(v[i].y)),
                                 fmaxf(fabsf(v[i].z), fabsf(v[i].w))));
    }
#pragma unroll
    for (int o = 16; o > 0; o >>= 1) amax = fmaxf(amax, __shfl_xor_sync(0xFFFFFFFFu, amax, o));
    __shared__ float wmax[8];
    if ((tid & 31) == 0) wmax[tid >> 5] = amax;
    __syncthreads();
    float am = wmax[0];
#pragma unroll
    for (int w = 1; w < 8; w++) am = fmaxf(am, wmax[w]);
    am = fmaxf(am, 1e-20f);

    float s1 = am * (1.0f / 127.0f), inv1 = 127.0f / am;
    float s2 = s1 * (1.0f / 254.0f), inv2 = 254.0f / s1;
    if (tid == 0) { g_s1[row] = s1; g_s2[row] = s2; }

    char4* q1o = reinterpret_cast<char4*>(g_q1 + (size_t)row * KDIM);
    char4* q2o = reinterpret_cast<char4*>(g_q2 + (size_t)row * KDIM);
#pragma unroll
    for (int i = 0; i < 4; i++) {
        float f[4] = {v[i].x, v[i].y, v[i].z, v[i].w};
        signed char c1[4], c2[4];
#pragma unroll
        for (int j = 0; j < 4; j++) {
            int q1 = __float2int_rn(f[j] * inv1);
            q1 = max(-127, min(127, q1));
            float r = f[j] - s1 * (float)q1;
            int q2 = __float2int_rn(r * inv2);
            q2 = max(-127, min(127, q2));
            c1[j] = (signed char)q1;
            c2[j] = (signed char)q2;
        }
        q1o[tid + i * 256] = make_char4(c1[0], c1[1], c1[2], c1[3]);
        q2o[tid + i * 256] = make_char4(c2[0], c2[1], c2[2], c2[3]);
    }
}

// ============================================================
// Fused GEMM, 3 main stages + double-buffered half-stage W staging.
// 384 threads: wid 0-7 consumers, wid 8-11 W producers.
// Producer per stage: 2 halves; each half: CP_WAIT1 (next half keeps
// flying) -> pack -> STS; reissue buffer 2 halves ahead.
// ============================================================
__global__ void __launch_bounds__(384, 1) Linear8bit_gemm(
    const __grid_constant__ CUtensorMap tm_q1,
    const __grid_constant__ CUtensorMap tm_q2,
    const void* __restrict__ wsrc,
    const float* __restrict__ f0,
    const float* __restrict__ f1,
    float* __restrict__ out)
{
    extern __shared__ __align__(1024) uint8_t smem_buf[];
    uint32_t sb = smem_u32(smem_buf);
    int tid = threadIdx.x, wid = tid >> 5, lane = tid & 31;
    int n0 = blockIdx.x * NTILE;
    int fmt = g_wfmt;

    if (tid == 0) {
        for (int s = 0; s < NSTAGES; s++) {
            mbar_init(sb + SM_FULL(s), 129);  // 1 expect_tx + 128 producer arrivals
            mbar_init(sb + SM_EMPTY(s), 8);   // 8 consumer warps
        }
    }
    asm volatile("fence.proxy.async.shared::cta;" ::: "memory");
    __syncthreads();

    int c[4][8][4];
#pragma unroll
    for (int i = 0; i < 4; i++)
#pragma unroll
        for (int j = 0; j < 8; j++)
#pragma unroll
            for (int q = 0; q < 4; q++) c[i][j][q] = 0;

    int ww = wid & 3;
    int wm = (ww & 1) * 64;
    int wn = (ww >> 1) * 64;

    if (wid >= 8) {
        int ptid = tid - 256;              // 0..127, owns W row ptid
        int pwarp = ptid >> 5;             // producer warp 0..3
        if (fmt == 1 || fmt == 2) {
            // ---- half-stage ping-pong cp.async producer ----
            const char* base = (const char*)wsrc;
            uint32_t stg = sb + WSTG0;
            // load half (kc,h) into buffer b: warp covers its 32 rows,
            // 2 rows per instruction (16 lanes per row's 256B segment)
            int rlo = pwarp * 32 + ((lane >> 4) ? 1 : 0);
            int cb  = (lane & 15) * 16;
#define LOAD_HALF(b, kc, h)                                                       \
            do {                                                                  \
                uint32_t _d = stg + (uint32_t)(b) * WSTG_HALF + cb;               \
                const char* _s = base + (size_t)(kc) * 512 + (size_t)(h) * 256 + cb; \
                for (int r = 0; r < 16; r++) {                                    \
                    int row = rlo + r * 2;                                        \
                    cpasync16(_d + (uint32_t)row * WROW,                          \
                              _s + (size_t)(n0 + row) * (KDIM * 4));              \
                }                                                                 \
                CP_COMMIT();                                                      \
            } while (0)

            LOAD_HALF(0, 0, 0);
            LOAD_HALF(1, 0, 1);

            int st = 0, ph = 1, buf = 0;
            uint32_t srow = stg + (uint32_t)ptid * WROW;
            uint32_t dbase = (uint32_t)ptid * 128;

            for (int kc = 0; kc < NKC; kc++) {
#pragma unroll
                for (int h = 0; h < 2; h++) {
                    CP_WAIT1();            // current half landed; next keeps flying
                    __syncwarp();
                    if (h == 0) {
                        mbar_wait(sb + SM_EMPTY(st), ph);   // ACQUIRE
                        if (ptid == 0) {
                            mbar_expect_tx(sb + SM_FULL(st), 2 * 128 * KC);
                            uint32_t sbase = sb + SM_STAGE0 + st * STAGE_BYTES;
                            tma2d(sbase + OFF_Q1, &tm_q1, kc * KC, 0, sb + SM_FULL(st));
                            tma2d(sbase + OFF_Q2, &tm_q2, kc * KC, 0, sb + SM_FULL(st));
                        }
                    }
                    uint32_t Wb = sb + SM_STAGE0 + st * STAGE_BYTES + OFF_W;
                    uint32_t sh = srow + (uint32_t)buf * WSTG_HALF;
                    // pack 256B -> 64B: output chunk j <- input chunks 4j..4j+3
#pragma unroll
                    for (int j = 0; j < 4; j++) {
                        uint32_t ow[4];
#pragma unroll
                        for (int t = 0; t < 4; t++) {
                            int4 v;
                            LDS128(v, sh + (uint32_t)(j * 4 + t) * 16);
                            if (fmt == 1) {
                                ow[t] = pack4i(v.x, v.y, v.z, v.w);
                            } else {
                                ow[t] = pack4i(__float2int_rn(__int_as_float(v.x)),
                                               __float2int_rn(__int_as_float(v.y)),
                                               __float2int_rn(__int_as_float(v.z)),
                                               __float2int_rn(__int_as_float(v.w)));
                            }
                        }
                        int4 o = make_int4(ow[0], ow[1], ow[2], ow[3]);
                        sts128(Wb + SWZ(dbase + h * 64 + j * 16), o);
                    }
                    if (h == 1) mbar_arrive(sb + SM_FULL(st));
                    __syncwarp();          // warp done reading buf before refill
                    // reissue this buffer 2 halves ahead
                    int nh = kc * 2 + h + 2;
                    if (nh < NKC * 2) LOAD_HALF(buf, nh >> 1, nh & 1);
                    else CP_COMMIT();      // keep group accounting consistent
                    buf ^= 1;
                }
                if (++st == NSTAGES) { st = 0; ph ^= 1; }
            }
#undef LOAD_HALF
        } else {
            // ---- LDG fallback (fmt 0 = packed int8, fmt 3 = bf16) ----
            int st = 0, ph = 1;
            for (int kc = 0; kc < NKC; kc++) {
                mbar_wait(sb + SM_EMPTY(st), ph);   // ACQUIRE
                if (ptid == 0) {
                    mbar_expect_tx(sb + SM_FULL(st), 2 * 128 * KC);
                    uint32_t sbase = sb + SM_STAGE0 + st * STAGE_BYTES;
                    tma2d(sbase + OFF_Q1, &tm_q1, kc * KC, 0, sb + SM_FULL(st));
                    tma2d(sbase + OFF_Q2, &tm_q2, kc * KC, 0, sb + SM_FULL(st));
                }
                uint32_t Wb = sb + SM_STAGE0 + st * STAGE_BYTES + OFF_W;
                uint32_t dbase = (uint32_t)ptid * 128;
                size_t e0 = (size_t)(n0 + ptid) * KDIM + (size_t)kc * KC;
                if (fmt == 3) {
                    const uint4* src = reinterpret_cast<const uint4*>(
                        (const uint16_t*)wsrc + e0);
#pragma unroll
                    for (int ch = 0; ch < 8; ch++) {
                        uint4 p0 = src[ch * 2], p1 = src[ch * 2 + 1];
                        int4 o;
                        o.x = pack4i(bf2i(p0.x & 0xFFFFu), bf2i(p0.x >> 16),
                                     bf2i(p0.y & 0xFFFFu), bf2i(p0.y >> 16));
                        o.y = pack4i(bf2i(p0.z & 0xFFFFu), bf2i(p0.z >> 16),
                                     bf2i(p0.w & 0xFFFFu), bf2i(p0.w >> 16));
                        o.z = pack4i(bf2i(p1.x & 0xFFFFu), bf2i(p1.x >> 16),
                                     bf2i(p1.y & 0xFFFFu), bf2i(p1.y >> 16));
                        o.w = pack4i(bf2i(p1.z & 0xFFFFu), bf2i(p1.z >> 16),
                                     bf2i(p1.w & 0xFFFFu), bf2i(p1.w >> 16));
                        sts128(Wb + SWZ(dbase + ch * 16), o);
                    }
                } else {
                    const int4* src = reinterpret_cast<const int4*>(
                        (const int8_t*)wsrc + e0);
#pragma unroll
                    for (int ch = 0; ch < 8; ch++) {
                        int4 o = src[ch];
                        sts128(Wb + SWZ(dbase + ch * 16), o);
                    }
                }
                mbar_arrive(sb + SM_FULL(st));
                if (++st == NSTAGES) { st = 0; ph ^= 1; }
            }
        }
    } else {
        // ---------- consumer warps (proven path, 3-stage cursor) ----------
        uint32_t offA = (wid >= 4) ? (uint32_t)OFF_Q2 : (uint32_t)OFF_Q1;
        int g = lane >> 3, idx = lane & 7;

        uint32_t aP[4], bP[4];
        {
            int rb = wm + idx + (g & 1) * 8;
            int kh = (g >> 1) * 16;
#pragma unroll
            for (int i = 0; i < 4; i++) {
                int row = rb + i * 16;
                aP[i] = sb + SM_STAGE0 + offA + row * 128 + (kh ^ ((row & 7) * 16));
            }
        }
        {
            int rb = wn + idx + (g >> 1) * 8;
            int kh = (g & 1) * 16;
#pragma unroll
            for (int j = 0; j < 4; j++) {
                int row = rb + j * 16;
                bP[j] = sb + SM_STAGE0 + OFF_W + row * 128 + (kh ^ ((row & 7) * 16));
            }
        }

        int stage = 0, ph = 0;
        for (int kc = 0; kc < NKC; kc++) {
            mbar_wait(sb + SM_FULL(stage), ph);
            uint32_t sdel = stage * STAGE_BYTES;
#pragma unroll
            for (int s = 0; s < 4; s++) {
                uint32_t a[4][4], b[4][4];
#pragma unroll
                for (int i = 0; i < 4; i++) LDMX4(a[i], (aP[i] + sdel) ^ (s * 32));
#pragma unroll
                for (int j = 0; j < 4; j++) LDMX4(b[j], (bP[j] + sdel) ^ (s * 32));
#pragma unroll
                for (int i = 0; i < 4; i++)
#pragma unroll
                    for (int jj = 0; jj < 8; jj++)
                        MMA_S8(c[i][jj], a[i], b[jj >> 1][(jj & 1) * 2],
                               b[jj >> 1][(jj & 1) * 2 + 1]);
            }
            if (lane == 0) mbar_arrive(sb + SM_EMPTY(stage));
            if (++stage == NSTAGES) { stage = 0; ph ^= 1; }
        }
    }

    // ---------- epilogue (proven path) ----------
    __syncthreads();
    int swap = g_swap;
    const float* wscale = swap ? f1 : f0;
    const float* bias   = swap ? f0 : f1;

    const int LDSF = 132;
    float* smemf = reinterpret_cast<float*>(smem_buf + SM_STAGE0);

    if (wid >= 4 && wid < 8) {
#pragma unroll
        for (int i = 0; i < 4; i++) {
#pragma unroll
            for (int j = 0; j < 8; j++) {
                int r0 = wm + i * 16 + (lane >> 2);
                int c0 = wn + j * 8 + (lane & 3) * 2;
                *reinterpret_cast<float2*>(&smemf[r0 * LDSF + c0]) =
                    make_float2((float)c[i][j][0], (float)c[i][j][1]);
                *reinterpret_cast<float2*>(&smemf[(r0 + 8) * LDSF + c0]) =
                    make_float2((float)c[i][j][2], (float)c[i][j][3]);
            }
        }
    }
    __syncthreads();

    if (wid < 4) {
#pragma unroll
        for (int i = 0; i < 4; i++) {
            int r0 = wm + i * 16 + (lane >> 2);
            float s1a = g_s1[r0],     s2a = g_s2[r0];
            float s1b = g_s1[r0 + 8], s2b = g_s2[r0 + 8];
#pragma unroll
            for (int j = 0; j < 8; j++) {
                int c0 = wn + j * 8 + (lane & 3) * 2;
                float2 wsc = *reinterpret_cast<const float2*>(wscale + n0 + c0);
                float2 bi  = *reinterpret_cast<const float2*>(bias + n0 + c0);
                wsc.x *= (1.0f / 127.0f);
                wsc.y *= (1.0f / 127.0f);
                float2 d2a = *reinterpret_cast<float2*>(&smemf[r0 * LDSF + c0]);
                float2 d2b = *reinterpret_cast<float2*>(&smemf[(r0 + 8) * LDSF + c0]);
                float2 oa, ob;
                oa.x = fmaf(fmaf(s2a, d2a.x, s1a * (float)c[i][j][0]), wsc.x, bi.x);
                oa.y = fmaf(fmaf(s2a, d2a.y, s1a * (float)c[i][j][1]), wsc.y, bi.y);
                ob.x = fmaf(fmaf(s2b, d2b.x, s1b * (float)c[i][j][2]), wsc.x, bi.x);
                ob.y = fmaf(fmaf(s2b, d2b.y, s1b * (float)c[i][j][3]), wsc.y, bi.y);
                *reinterpret_cast<float2*>(out + (size_t)r0 * NDIM + n0 + c0) = oa;
                *reinterpret_cast<float2*>(out + (size_t)(r0 + 8) * NDIM + n0 + c0) = ob;
            }
        }
    }
}

typedef CUresult (*PFN_encodeTiled)(
    CUtensorMap*, CUtensorMapDataType, cuuint32_t, void*,
    const cuuint64_t*, const cuuint64_t*, const cuuint32_t*, const cuuint32_t*,
    CUtensorMapInterleave, CUtensorMapSwizzle, CUtensorMapL2promotion,
    CUtensorMapFloatOOBfill);

static void make_map_u8(PFN_encodeTiled enc, CUtensorMap* m, void* base,
                        uint64_t d0, uint64_t d1) {
    cuuint64_t dims[2]    = {d0, d1};
    cuuint64_t strides[1] = {d0};
    cuuint32_t box[2]     = {128, 128};
    cuuint32_t es[2]      = {1, 1};
    enc(m, CU_TENSOR_MAP_DATA_TYPE_UINT8, 2, base, dims, strides, box, es,
        CU_TENSOR_MAP_INTERLEAVE_NONE, CU_TENSOR_MAP_SWIZZLE_128B,
        CU_TENSOR_MAP_L2_PROMOTION_L2_128B, CU_TENSOR_MAP_FLOAT_OOB_FILL_NONE);
}

extern "C" void kernel_launch(void* const* d_in, const int* in_sizes, int n_in,
                              void* d_out, int out_size) {
    const float* x = nullptr; const void* w = nullptr;
    const float* f0 = nullptr; const float* f1 = nullptr;
    for (int i = 0; i < n_in; i++) {
        if (in_sizes[i] == MROWS * KDIM)      x = (const float*)d_in[i];
        else if (in_sizes[i] == NDIM * KDIM)  w = d_in[i];
        else if (in_sizes[i] == NDIM) {
            if (!f0) f0 = (const float*)d_in[i];
            else     f1 = (const float*)d_in[i];
        }
    }
    float* out = (float*)d_out;

    void* pq1 = nullptr; void* pq2 = nullptr;
    cudaGetSymbolAddress(&pq1, g_q1);
    cudaGetSymbolAddress(&pq2, g_q2);

    PFN_encodeTiled enc = nullptr;
    cudaDriverEntryPointQueryResult qr;
    cudaGetDriverEntryPoint("cuTensorMapEncodeTiled", (void**)&enc,
                            cudaEnableDefault, &qr);

    CUtensorMap tq1, tq2;
    make_map_u8(enc, &tq1, pq1, KDIM, MROWS);
    make_map_u8(enc, &tq2, pq2, KDIM, MROWS);

    cudaFuncSetAttribute(Linear8bit_gemm,
                         cudaFuncAttributeMaxDynamicSharedMemorySize, SMEM_TOTAL);

    quantize_x_kernel<<<130, 256>>>(x, (const int*)w, f0);
    Linear8bit_gemm<<<NDIM / NTILE, 384, SMEM_TOTAL>>>(tq1, tq2, w, f0, f1, out);
}

// round 16
// speedup vs baseline: 4.1848x; 1.0623x over previous
#include <cuda_runtime.h>
#include <cuda.h>
#include <cstdint>

#define MROWS 128
#define KDIM  4096
#define NDIM  16384
#define NTILE 128
#define KC    128
#define NKC   (KDIM / KC)
#define NSTAGES 3

#define SM_FULLA(s) (16 + (s) * 8)
#define SM_FULLB(s) (48 + (s) * 8)
#define SM_EMPTY(s) (88 + (s) * 8)
#define STAGE_BYTES (3 * 128 * KC)              // 48KB
#define SM_STAGE0   1024
#define OFF_Q1 0
#define OFF_Q2 (128 * KC)
#define OFF_W  (2 * 128 * KC)
#define QROW        144                          // 128B quarter + 16B pad
#define QSTG        (128 * QROW)                 // 18432
#define WSTG0       (SM_STAGE0 + NSTAGES * STAGE_BYTES)   // 148480
#define SMEM_TOTAL  (WSTG0 + 4 * QSTG)           // 222208 <= 232448

#define SWZ(o) ((uint32_t)(o) ^ ((((uint32_t)(o)) >> 3) & 0x70u))

__device__ __align__(128) int8_t g_q1[MROWS * KDIM];
__device__ __align__(128) int8_t g_q2[MROWS * KDIM];
__device__ float g_s1[MROWS];
__device__ float g_s2[MROWS];
__device__ int   g_swap;
__device__ int   g_wfmt;   // 0=int8 packed, 1=int32, 2=float32, 3=bf16

__device__ __forceinline__ uint32_t smem_u32(const void* p) {
    uint32_t a;
    asm("{ .reg .u64 t; cvta.to.shared.u64 t, %1; cvt.u32.u64 %0, t; }" : "=r"(a) : "l"(p));
    return a;
}
__device__ __forceinline__ void mbar_init(uint32_t m, uint32_t c) {
    asm volatile("mbarrier.init.shared.b64 [%0], %1;" :: "r"(m), "r"(c) : "memory");
}
__device__ __forceinline__ void mbar_expect_tx(uint32_t m, uint32_t b) {
    asm volatile("mbarrier.arrive.expect_tx.shared.b64 _, [%0], %1;" :: "r"(m), "r"(b) : "memory");
}
__device__ __forceinline__ void mbar_arrive(uint32_t m) {
    asm volatile("mbarrier.arrive.shared.b64 _, [%0];" :: "r"(m) : "memory");
}
// acquire wait: REQUIRED before any generic ld/st.shared that follows
__device__ __forceinline__ void mbar_wait(uint32_t m, uint32_t p) {
    asm volatile(
        "{\n\t.reg .pred P1;\n\tW_%=:\n\t"
        "mbarrier.try_wait.parity.acquire.cta.shared::cta.b64 P1, [%0], %1, 0x989680;\n\t"
        "@P1 bra.uni D_%=;\n\tbra.uni W_%=;\n\tD_%=:\n\t}"
        :: "r"(m), "r"(p) : "memory");
}
__device__ __forceinline__ void tma2d(uint32_t d, const CUtensorMap* t,
                                      int32_t cx, int32_t cy, uint32_t m) {
    asm volatile(
        "cp.async.bulk.tensor.2d.shared::cta.global.tile.mbarrier::complete_tx::bytes "
        "[%0], [%1, {%2, %3}], [%4];"
        :: "r"(d), "l"(t), "r"(cx), "r"(cy), "r"(m) : "memory");
}
__device__ __forceinline__ void cpasync16(uint32_t dst, const void* src) {
    asm volatile("cp.async.cg.shared.global [%0], [%1], 16;" :: "r"(dst), "l"(src) : "memory");
}
#define CP_COMMIT() asm volatile("cp.async.commit_group;" ::: "memory")
#define CP_WAIT3()  asm volatile("cp.async.wait_group 3;" ::: "memory")

__device__ __forceinline__ void sts128(uint32_t addr, int4 v) {
    asm volatile("st.shared.v4.b32 [%0], {%1,%2,%3,%4};"
                 :: "r"(addr), "r"(v.x), "r"(v.y), "r"(v.z), "r"(v.w) : "memory");
}
#define LDS128(v, a)                                                          \
    asm volatile("ld.shared.v4.b32 {%0,%1,%2,%3}, [%4];"                      \
                 : "=r"((v).x), "=r"((v).y), "=r"((v).z), "=r"((v).w) : "r"(a))

#define LDMX4(r, addr)                                                           \
    asm volatile("ldmatrix.sync.aligned.m8n8.x4.shared.b16 {%0,%1,%2,%3}, [%4];" \
                 : "=r"((r)[0]), "=r"((r)[1]), "=r"((r)[2]), "=r"((r)[3])        \
                 : "r"(addr))

#define MMA_S8(c, a, b0, b1)                                                  \
    asm volatile("mma.sync.aligned.m16n8k32.row.col.s32.s8.s8.s32 "           \
                 "{%0,%1,%2,%3}, {%4,%5,%6,%7}, {%8,%9}, {%0,%1,%2,%3};"      \
                 : "+r"((c)[0]), "+r"((c)[1]), "+r"((c)[2]), "+r"((c)[3])     \
                 : "r"((a)[0]), "r"((a)[1]), "r"((a)[2]), "r"((a)[3]),        \
                   "r"(b0), "r"(b1))

__device__ __forceinline__ int pack4i(int x0, int x1, int x2, int x3) {
    return (x0 & 0xFF) | ((x1 & 0xFF) << 8) | ((x2 & 0xFF) << 16) | ((x3 & 0xFF) << 24);
}
__device__ __forceinline__ int bf2i(uint32_t h) {
    return __float2int_rn(__uint_as_float(h << 16));
}

// ============================================================
// quantize + detect fused (blocks 0-127 quantize, 128/129 detect)
// ============================================================
__global__ void __launch_bounds__(256) quantize_x_kernel(const float* __restrict__ x,
                                                         const int* __restrict__ wsrc,
                                                         const float* __restrict__ f0) {
    int tid = threadIdx.x;
    if (blockIdx.x == 128) {
        int ok_i32 = 1, ok_f32 = 1, ok_bf16 = 1;
#pragma unroll
        for (int t = 0; t < 4; t++) {
            int w = wsrc[tid + t * 256];
            if (w < -128 || w > 127) ok_i32 = 0;
            float f = __int_as_float(w);
            if (!(f == rintf(f) && fabsf(f) <= 127.0f)) ok_f32 = 0;
            float h0 = __uint_as_float(((uint32_t)w & 0xFFFFu) << 16);
            float h1 = __uint_as_float(((uint32_t)w >> 16) << 16);
            if (!(h0 == rintf(h0) && fabsf(h0) <= 127.0f)) ok_bf16 = 0;
            if (!(h1 == rintf(h1) && fabsf(h1) <= 127.0f)) ok_bf16 = 0;
        }
        ok_i32  = __syncthreads_and(ok_i32);
        ok_f32  = __syncthreads_and(ok_f32);
        ok_bf16 = __syncthreads_and(ok_bf16);
        if (tid == 0) g_wfmt = ok_i32 ? 1 : (ok_f32 ? 2 : (ok_bf16 ? 3 : 0));
        return;
    }
    if (blockIdx.x == 129) {
        __shared__ int neg;
        if (tid == 0) neg = 0;
        __syncthreads();
        int found = 0;
        for (int i = tid; i < NDIM; i += 256) found |= (f0[i] < 0.0f);
        if (__any_sync(0xFFFFFFFFu, found) && (tid & 31) == 0) atomicOr(&neg, 1);
        __syncthreads();
        if (tid == 0) g_swap = neg;
        return;
    }

    int row = blockIdx.x;
    const float4* xr = reinterpret_cast<const float4*>(x + (size_t)row * KDIM);
    float4 v[4];
    float amax = 0.f;
#pragma unroll
    for (int i = 0; i < 4; i++) {
        v[i] = xr[tid + i * 256];
        amax = fmaxf(amax, fmaxf(fmaxf(fabsf(v[i].x), fabsf(v[i].y)),
                                 fmaxf(fabsf(v[i].z), fabsf(v[i].w))));
    }
#pragma unroll
    for (int o = 16; o > 0; o >>= 1) amax = fmaxf(amax, __shfl_xor_sync(0xFFFFFFFFu, amax, o));
    __shared__ float wmax[8];
    if ((tid & 31) == 0) wmax[tid >> 5] = amax;
    __syncthreads();
    float am = wmax[0];
#pragma unroll
    for (int w = 1; w < 8; w++) am = fmaxf(am, wmax[w]);
    am = fmaxf(am, 1e-20f);

    float s1 = am * (1.0f / 127.0f), inv1 = 127.0f / am;
    float s2 = s1 * (1.0f / 254.0f), inv2 = 254.0f / s1;
    if (tid == 0) { g_s1[row] = s1; g_s2[row] = s2; }

    char4* q1o = reinterpret_cast<char4*>(g_q1 + (size_t)row * KDIM);
    char4* q2o = reinterpret_cast<char4*>(g_q2 + (size_t)row * KDIM);
#pragma unroll
    for (int i = 0; i < 4; i++) {
        float f[4] = {v[i].x, v[i].y, v[i].z, v[i].w};
        signed char c1[4], c2[4];
#pragma unroll
        for (int j = 0; j < 4; j++) {
            int q1 = __float2int_rn(f[j] * inv1);
            q1 = max(-127, min(127, q1));
            float r = f[j] - s1 * (float)q1;
            int q2 = __float2int_rn(r * inv2);
            q2 = max(-127, min(127, q2));
            c1[j] = (signed char)q1;
            c2[j] = (signed char)q2;
        }
        q1o[tid + i * 256] = make_char4(c1[0], c1[1], c1[2], c1[3]);
        q2o[tid + i * 256] = make_char4(c2[0], c2[1], c2[2], c2[3]);
    }
}

// ============================================================
// Fused GEMM. 3 main stages, split FULLA/FULLB barriers, and a
// 4-buffer quarter-granularity cp.async staging ring.
// FIX vs R15: preload all 4 ring buffers and wait_group 3, so the
// buffer rotation (mod 4) matches the load schedule exactly
// (R15 preloaded only 3 -> quarter<->buffer mapping shifted, garbage W).
// Prefetch distance = 3 quarters (~DRAM latency) -> producer never stalls.
// FULLA = q-TMA tx + W logical bytes [0,64) (ksteps 0-1);
// FULLB = W logical bytes [64,128) (ksteps 2-3).
// ============================================================
__global__ void __launch_bounds__(384, 1) Linear8bit_gemm(
    const __grid_constant__ CUtensorMap tm_q1,
    const __grid_constant__ CUtensorMap tm_q2,
    const void* __restrict__ wsrc,
    const float* __restrict__ f0,
    const float* __restrict__ f1,
    float* __restrict__ out)
{
    extern __shared__ __align__(1024) uint8_t smem_buf[];
    uint32_t sb = smem_u32(smem_buf);
    int tid = threadIdx.x, wid = tid >> 5, lane = tid & 31;
    int n0 = blockIdx.x * NTILE;
    int fmt = g_wfmt;

    if (tid == 0) {
        for (int s = 0; s < NSTAGES; s++) {
            mbar_init(sb + SM_FULLA(s), 129);  // expect_tx + 128 producer arrivals
            mbar_init(sb + SM_FULLB(s), 128);  // 128 producer arrivals
            mbar_init(sb + SM_EMPTY(s), 8);    // 8 consumer warps
        }
    }
    asm volatile("fence.proxy.async.shared::cta;" ::: "memory");
    __syncthreads();

    int c[4][8][4];
#pragma unroll
    for (int i = 0; i < 4; i++)
#pragma unroll
        for (int j = 0; j < 8; j++)
#pragma unroll
            for (int q = 0; q < 4; q++) c[i][j][q] = 0;

    int ww = wid & 3;
    int wm = (ww & 1) * 64;
    int wn = (ww >> 1) * 64;

    if (wid >= 8) {
        int ptid = tid - 256;              // 0..127, owns W row ptid
        int pwarp = ptid >> 5;             // producer warp 0..3
        if (fmt == 1 || fmt == 2) {
            // ---- quarter-ring cp.async producer (ring size 4) ----
            const char* base = (const char*)wsrc;
            uint32_t stg = sb + WSTG0;
            int rin = lane >> 3;           // 0..3
            int cbq = (lane & 7) * 16;     // byte within 128B quarter
            // load quarter gq (global, 0..NKC*4-1) into ring buffer b
#define LOAD_Q(b, gq)                                                              \
            do {                                                                   \
                uint32_t _d = stg + (uint32_t)(b) * QSTG + cbq;                    \
                const char* _s = base + (size_t)(gq) * 128 + cbq;                  \
                for (int r = 0; r < 8; r++) {                                      \
                    int row = pwarp * 32 + r * 4 + rin;                            \
                    cpasync16(_d + (uint32_t)row * QROW,                           \
                              _s + (size_t)(n0 + row) * (KDIM * 4));               \
                }                                                                  \
                CP_COMMIT();                                                       \
            } while (0)

            LOAD_Q(0, 0); LOAD_Q(1, 1); LOAD_Q(2, 2); LOAD_Q(3, 3);
            int qnext = 4, buf = 0;

            int st = 0, ph = 1;
            uint32_t srow = stg + (uint32_t)ptid * QROW;
            uint32_t dbase = (uint32_t)ptid * 128;

            for (int kc = 0; kc < NKC; kc++) {
#pragma unroll
                for (int q = 0; q < 4; q++) {
                    CP_WAIT3();            // current buf landed (3 newer in flight)
                    __syncwarp();
                    if (q == 0) {
                        mbar_wait(sb + SM_EMPTY(st), ph);   // ACQUIRE
                        if (ptid == 0) {
                            mbar_expect_tx(sb + SM_FULLA(st), 2 * 128 * KC);
                            uint32_t sbase = sb + SM_STAGE0 + st * STAGE_BYTES;
                            tma2d(sbase + OFF_Q1, &tm_q1, kc * KC, 0, sb + SM_FULLA(st));
                            tma2d(sbase + OFF_Q2, &tm_q2, kc * KC, 0, sb + SM_FULLA(st));
                        }
                    }
                    uint32_t Wb = sb + SM_STAGE0 + st * STAGE_BYTES + OFF_W;
                    uint32_t sh = srow + (uint32_t)buf * QSTG;
                    // pack 128B widened -> 32B packed (2 output 16B chunks)
#pragma unroll
                    for (int c2 = 0; c2 < 2; c2++) {
                        uint32_t ow[4];
#pragma unroll
                        for (int t = 0; t < 4; t++) {
                            int4 v;
                            LDS128(v, sh + (uint32_t)(c2 * 4 + t) * 16);
                            if (fmt == 1) {
                                ow[t] = pack4i(v.x, v.y, v.z, v.w);
                            } else {
                                ow[t] = pack4i(__float2int_rn(__int_as_float(v.x)),
                                               __float2int_rn(__int_as_float(v.y)),
                                               __float2int_rn(__int_as_float(v.z)),
                                               __float2int_rn(__int_as_float(v.w)));
                            }
                        }
                        int4 o = make_int4(ow[0], ow[1], ow[2], ow[3]);
                        sts128(Wb + SWZ(dbase + q * 32 + c2 * 16), o);
                    }
                    if (q == 1) mbar_arrive(sb + SM_FULLA(st));
                    if (q == 3) mbar_arrive(sb + SM_FULLB(st));
                    __syncwarp();          // warp done reading buf before refill
                    if (qnext < NKC * 4) LOAD_Q(buf, qnext);
                    else CP_COMMIT();      // keep group accounting consistent
                    qnext++;
                    buf = (buf + 1) & 3;
                }
                if (++st == NSTAGES) { st = 0; ph ^= 1; }
            }
#undef LOAD_Q
        } else {
            // ---- LDG fallback (fmt 0 = packed int8, fmt 3 = bf16) ----
            int st = 0, ph = 1;
            for (int kc = 0; kc < NKC; kc++) {
                mbar_wait(sb + SM_EMPTY(st), ph);   // ACQUIRE
                if (ptid == 0) {
                    mbar_expect_tx(sb + SM_FULLA(st), 2 * 128 * KC);
                    uint32_t sbase = sb + SM_STAGE0 + st * STAGE_BYTES;
                    tma2d(sbase + OFF_Q1, &tm_q1, kc * KC, 0, sb + SM_FULLA(st));
                    tma2d(sbase + OFF_Q2, &tm_q2, kc * KC, 0, sb + SM_FULLA(st));
                }
                uint32_t Wb = sb + SM_STAGE0 + st * STAGE_BYTES + OFF_W;
                uint32_t dbase = (uint32_t)ptid * 128;
                size_t e0 = (size_t)(n0 + ptid) * KDIM + (size_t)kc * KC;
                if (fmt == 3) {
                    const uint4* src = reinterpret_cast<const uint4*>(
                        (const uint16_t*)wsrc + e0);
#pragma unroll
                    for (int ch = 0; ch < 8; ch++) {
                        uint4 p0 = src[ch * 2], p1 = src[ch * 2 + 1];
                        int4 o;
                        o.x = pack4i(bf2i(p0.x & 0xFFFFu), bf2i(p0.x >> 16),
                                     bf2i(p0.y & 0xFFFFu), bf2i(p0.y >> 16));
                        o.y = pack4i(bf2i(p0.z & 0xFFFFu), bf2i(p0.z >> 16),
                                     bf2i(p0.w & 0xFFFFu), bf2i(p0.w >> 16));
                        o.z = pack4i(bf2i(p1.x & 0xFFFFu), bf2i(p1.x >> 16),
                                     bf2i(p1.y & 0xFFFFu), bf2i(p1.y >> 16));
                        o.w = pack4i(bf2i(p1.z & 0xFFFFu), bf2i(p1.z >> 16),
                                     bf2i(p1.w & 0xFFFFu), bf2i(p1.w >> 16));
                        sts128(Wb + SWZ(dbase + ch * 16), o);
                    }
                } else {
                    const int4* src = reinterpret_cast<const int4*>(
                        (const int8_t*)wsrc + e0);
#pragma unroll
                    for (int ch = 0; ch < 8; ch++) {
                        int4 o = src[ch];
                        sts128(Wb + SWZ(dbase + ch * 16), o);
                    }
                }
                mbar_arrive(sb + SM_FULLA(st));
                mbar_arrive(sb + SM_FULLB(st));
                if (++st == NSTAGES) { st = 0; ph ^= 1; }
            }
        }
    } else {
        // ---------- consumer warps (split-barrier, 3-stage cursor) ----------
        uint32_t offA = (wid >= 4) ? (uint32_t)OFF_Q2 : (uint32_t)OFF_Q1;
        int g = lane >> 3, idx = lane & 7;

        uint32_t aP[4], bP[4];
        {
            int rb = wm + idx + (g & 1) * 8;
            int kh = (g >> 1) * 16;
#pragma unroll
            for (int i = 0; i < 4; i++) {
                int row = rb + i * 16;
                aP[i] = sb + SM_STAGE0 + offA + row * 128 + (kh ^ ((row & 7) * 16));
            }
        }
        {
            int rb = wn + idx + (g >> 1) * 8;
            int kh = (g & 1) * 16;
#pragma unroll
            for (int j = 0; j < 4; j++) {
                int row = rb + j * 16;
                bP[j] = sb + SM_STAGE0 + OFF_W + row * 128 + (kh ^ ((row & 7) * 16));
            }
        }

        int stage = 0, ph = 0;
        for (int kc = 0; kc < NKC; kc++) {
            uint32_t sdel = stage * STAGE_BYTES;
            mbar_wait(sb + SM_FULLA(stage), ph);
#pragma unroll
            for (int s = 0; s < 4; s++) {
                if (s == 2) mbar_wait(sb + SM_FULLB(stage), ph);
                uint32_t a[4][4], b[4][4];
#pragma unroll
                for (int i = 0; i < 4; i++) LDMX4(a[i], (aP[i] + sdel) ^ (s * 32));
#pragma unroll
                for (int j = 0; j < 4; j++) LDMX4(b[j], (bP[j] + sdel) ^ (s * 32));
#pragma unroll
                for (int i = 0; i < 4; i++)
#pragma unroll
                    for (int jj = 0; jj < 8; jj++)
                        MMA_S8(c[i][jj], a[i], b[jj >> 1][(jj & 1) * 2],
                               b[jj >> 1][(jj & 1) * 2 + 1]);
            }
            if (lane == 0) mbar_arrive(sb + SM_EMPTY(stage));
            if (++stage == NSTAGES) { stage = 0; ph ^= 1; }
        }
    }

    // ---------- epilogue (proven path) ----------
    __syncthreads();
    int swap = g_swap;
    const float* wscale = swap ? f1 : f0;
    const float* bias   = swap ? f0 : f1;

    const int LDSF = 132;
    float* smemf = reinterpret_cast<float*>(smem_buf + SM_STAGE0);

    if (wid >= 4 && wid < 8) {
#pragma unroll
        for (int i = 0; i < 4; i++) {
#pragma unroll
            for (int j = 0; j < 8; j++) {
                int r0 = wm + i * 16 + (lane >> 2);
                int c0 = wn + j * 8 + (lane & 3) * 2;
                *reinterpret_cast<float2*>(&smemf[r0 * LDSF + c0]) =
                    make_float2((float)c[i][j][0], (float)c[i][j][1]);
                *reinterpret_cast<float2*>(&smemf[(r0 + 8) * LDSF + c0]) =
                    make_float2((float)c[i][j][2], (float)c[i][j][3]);
            }
        }
    }
    __syncthreads();

    if (wid < 4) {
#pragma unroll
        for (int i = 0; i < 4; i++) {
            int r0 = wm + i * 16 + (lane >> 2);
            float s1a = g_s1[r0],     s2a = g_s2[r0];
            float s1b = g_s1[r0 + 8], s2b = g_s2[r0 + 8];
#pragma unroll
            for (int j = 0; j < 8; j++) {
                int c0 = wn + j * 8 + (lane & 3) * 2;
                float2 wsc = *reinterpret_cast<const float2*>(wscale + n0 + c0);
                float2 bi  = *reinterpret_cast<const float2*>(bias + n0 + c0);
                wsc.x *= (1.0f / 127.0f);
                wsc.y *= (1.0f / 127.0f);
                float2 d2a = *reinterpret_cast<float2*>(&smemf[r0 * LDSF + c0]);
                float2 d2b = *reinterpret_cast<float2*>(&smemf[(r0 + 8) * LDSF + c0]);
                float2 oa, ob;
                oa.x = fmaf(fmaf(s2a, d2a.x, s1a * (float)c[i][j][0]), wsc.x, bi.x);
                oa.y = fmaf(fmaf(s2a, d2a.y, s1a * (float)c[i][j][1]), wsc.y, bi.y);
                ob.x = fmaf(fmaf(s2b, d2b.x, s1b * (float)c[i][j][2]), wsc.x, bi.x);
                ob.y = fmaf(fmaf(s2b, d2b.y, s1b * (float)c[i][j][3]), wsc.y, bi.y);
                *reinterpret_cast<float2*>(out + (size_t)r0 * NDIM + n0 + c0) = oa;
                *reinterpret_cast<float2*>(out + (size_t)(r0 + 8) * NDIM + n0 + c0) = ob;
            }
        }
    }
}

typedef CUresult (*PFN_encodeTiled)(
    CUtensorMap*, CUtensorMapDataType, cuuint32_t, void*,
    const cuuint64_t*, const cuuint64_t*, const cuuint32_t*, const cuuint32_t*,
    CUtensorMapInterleave, CUtensorMapSwizzle, CUtensorMapL2promotion,
    CUtensorMapFloatOOBfill);

static void make_map_u8(PFN_encodeTiled enc, CUtensorMap* m, void* base,
                        uint64_t d0, uint64_t d1) {
    cuuint64_t dims[2]    = {d0, d1};
    cuuint64_t strides[1] = {d0};
    cuuint32_t box[2]     = {128, 128};
    cuuint32_t es[2]      = {1, 1};
    enc(m, CU_TENSOR_MAP_DATA_TYPE_UINT8, 2, base, dims, strides, box, es,
        CU_TENSOR_MAP_INTERLEAVE_NONE, CU_TENSOR_MAP_SWIZZLE_128B,
        CU_TENSOR_MAP_L2_PROMOTION_L2_128B, CU_TENSOR_MAP_FLOAT_OOB_FILL_NONE);
}

extern "C" void kernel_launch(void* const* d_in, const int* in_sizes, int n_in,
                              void* d_out, int out_size) {
    const float* x = nullptr; const void* w = nullptr;
    const float* f0 = nullptr; const float* f1 = nullptr;
    for (int i = 0; i < n_in; i++) {
        if (in_sizes[i] == MROWS * KDIM)      x = (const float*)d_in[i];
        else if (in_sizes[i] == NDIM * KDIM)  w = d_in[i];
        else if (in_sizes[i] == NDIM) {
            if (!f0) f0 = (const float*)d_in[i];
            else     f1 = (const float*)d_in[i];
        }
    }
    float* out = (float*)d_out;

    void* pq1 = nullptr; void* pq2 = nullptr;
    cudaGetSymbolAddress(&pq1, g_q1);
    cudaGetSymbolAddress(&pq2, g_q2);

    PFN_encodeTiled enc = nullptr;
    cudaDriverEntryPointQueryResult qr;
    cudaGetDriverEntryPoint("cuTensorMapEncodeTiled", (void**)&enc,
                            cudaEnableDefault, &qr);

    CUtensorMap tq1, tq2;
    make_map_u8(enc, &tq1, pq1, KDIM, MROWS);
    make_map_u8(enc, &tq2, pq2, KDIM, MROWS);

    cudaFuncSetAttribute(Linear8bit_gemm,
                         cudaFuncAttributeMaxDynamicSharedMemorySize, SMEM_TOTAL);

    quantize_x_kernel<<<130, 256>>>(x, (const int*)w, f0);
    Linear8bit_gemm<<<NDIM / NTILE, 384, SMEM_TOTAL>>>(tq1, tq2, w, f0, f1, out);
}